// round 13
// baseline (speedup 1.0000x reference)
#include <cuda_runtime.h>
#include <cuda_fp16.h>

// LightGCN propagation — gather formulation, fp16 sources, instruction-lean:
//   * fp16 embedding storage: 38.4MB table L2-resident, one 128B line/edge
//   * 16 lanes per row, uniform edge-entry loads (2 edges per warp instr)
//   * quad-entry ld.global.nc.L2::evict_first.v4.b64 (4 edges / 32B load)
//   * packed fma.rn.f32x2 accumulation (2 FMA2 per edge-lane, not 4 FFMA)
// fp32 accumulation in registers; fp16 layer outputs; fp32 final mean.
//
//   e0 = concat(user_emb, item_emb)   (N = 300000, D = 64)
//   e_{l+1}[r] = sum_{e: rows[e]==r} vals[e] * e_l[cols[e]]
//   out = (e0 + e1 + e2 + e3) / 4

#define DIM      64
#define DIM4     16              // 4-element groups per row
#define PAD_W    32              // padded CSR width (deg ~ Poisson(13.3))
#define NMAX     300000
#define OVF_CAP  4096
#define TPB      256

// ---- static scratch (alloc-free rule) -------------------------------------
__device__ int   g_cnt[NMAX];                      // per-row degree/cursor
__device__ uint2 g_list[(size_t)NMAX * PAD_W];     // {col, val_bits}  76.8MB
__device__ int   g_ovf_cnt;
__device__ int4  g_ovf[OVF_CAP];                   // {row, col, val_bits, 0}
__device__ float g_e0[(size_t)NMAX * DIM];         // e0 fp32 (for final mean)
__device__ uint2 g_h0[(size_t)NMAX * DIM4];        // e0 fp16 (gather source)
__device__ uint2 g_h1[(size_t)NMAX * DIM4];        // e1 fp16
__device__ uint2 g_h2[(size_t)NMAX * DIM4];        // e2 fp16

// ---- helpers ---------------------------------------------------------------
__device__ __forceinline__ uint2 f4_to_h4(float4 v) {
    __half2 a = __floats2half2_rn(v.x, v.y);
    __half2 b = __floats2half2_rn(v.z, v.w);
    uint2 r;
    r.x = *reinterpret_cast<unsigned*>(&a);
    r.y = *reinterpret_cast<unsigned*>(&b);
    return r;
}
__device__ __forceinline__ float2 h2_to_f2(unsigned h) {
    return __half22float2(*reinterpret_cast<__half2*>(&h));
}
// half2 (32b) -> packed f32x2 in a 64b register pair
__device__ __forceinline__ unsigned long long h2_to_fx2(unsigned h) {
    unsigned long long r;
    asm("{\n\t"
        ".reg .b16 lo, hi;\n\t"
        ".reg .f32 flo, fhi;\n\t"
        "mov.b32 {lo, hi}, %1;\n\t"
        "cvt.f32.f16 flo, lo;\n\t"
        "cvt.f32.f16 fhi, hi;\n\t"
        "mov.b64 %0, {flo, fhi};\n\t"
        "}" : "=l"(r) : "r"(h));
    return r;
}
__device__ __forceinline__ void fma2(unsigned long long& acc,
                                     unsigned long long x,
                                     unsigned long long v) {
    asm("fma.rn.f32x2 %0, %1, %2, %0;" : "+l"(acc) : "l"(x), "l"(v));
}
__device__ __forceinline__ unsigned long long dup_hi32(unsigned long long e) {
    // entry u64 = col | (val<<32)  ->  {val, val} packed f32x2 multiplier
    unsigned long long r;
    unsigned v = (unsigned)(e >> 32);
    asm("mov.b64 %0, {%1, %1};" : "=l"(r) : "r"(v));
    return r;
}
__device__ __forceinline__ float2 unpack_fx2(unsigned long long a) {
    float2 r;
    asm("mov.b64 {%0, %1}, %2;" : "=f"(r.x), "=f"(r.y) : "l"(a));
    return r;
}
// 256-bit entry load: 4 edge entries, L2::evict_first (streaming edge list)
__device__ __forceinline__ void ldg_ef4(const uint2* p,
                                        unsigned long long& e0,
                                        unsigned long long& e1,
                                        unsigned long long& e2,
                                        unsigned long long& e3) {
    asm("ld.global.nc.L2::evict_first.v4.b64 {%0,%1,%2,%3}, [%4];"
        : "=l"(e0), "=l"(e1), "=l"(e2), "=l"(e3) : "l"(p));
}

// ---- prep: zero counters + e0 -> fp32 copy + fp16 copy ---------------------
__global__ void lg_prep(const float4* __restrict__ user,
                        const float4* __restrict__ item,
                        int n_user4, int n4, int n_rows) {
    int i = blockIdx.x * blockDim.x + threadIdx.x;
    if (i < n_rows) g_cnt[i] = 0;
    if (i == 0) g_ovf_cnt = 0;
    if (i >= n4) return;
    float4 v = (i < n_user4) ? user[i] : item[i - n_user4];
    reinterpret_cast<float4*>(g_e0)[i] = v;
    g_h0[i] = f4_to_h4(v);
}

// ---- build padded CSR, 4 edges per thread ----------------------------------
__global__ void lg_build4(const int4* __restrict__ rows4,
                          const int4* __restrict__ cols4,
                          const float4* __restrict__ vals4,
                          const int* __restrict__ rows,
                          const int* __restrict__ cols,
                          const float* __restrict__ vals,
                          int nq, int nnz) {
    int i = blockIdx.x * blockDim.x + threadIdx.x;
    if (i < nq) {
        int4   r = rows4[i];
        int4   c = cols4[i];
        float4 v = vals4[i];
        int rr[4] = {r.x, r.y, r.z, r.w};
        int cc[4] = {c.x, c.y, c.z, c.w};
        float vv[4] = {v.x, v.y, v.z, v.w};
        #pragma unroll
        for (int k = 0; k < 4; k++) {
            int pos = atomicAdd(&g_cnt[rr[k]], 1);
            if (pos < PAD_W) {
                g_list[(size_t)rr[k] * PAD_W + pos] =
                    make_uint2((unsigned)cc[k], __float_as_uint(vv[k]));
            } else {
                int o = atomicAdd(&g_ovf_cnt, 1);
                if (o < OVF_CAP)
                    g_ovf[o] = make_int4(rr[k], cc[k], __float_as_int(vv[k]), 0);
            }
        }
    }
    if (i == 0) {                                   // scalar tail (<= 3 edges)
        for (int e = nq * 4; e < nnz; e++) {
            int pos = atomicAdd(&g_cnt[rows[e]], 1);
            if (pos < PAD_W) {
                g_list[(size_t)rows[e] * PAD_W + pos] =
                    make_uint2((unsigned)cols[e], __float_as_uint(vals[e]));
            } else {
                int o = atomicAdd(&g_ovf_cnt, 1);
                if (o < OVF_CAP)
                    g_ovf[o] = make_int4(rows[e], cols[e],
                                         __float_as_int(vals[e]), 0);
            }
        }
    }
}

// ---- per-row gather core: 16 lanes/row, fp16 src, packed f32x2 accum -------
__device__ __forceinline__ float4 row_gather(const uint2* __restrict__ src,
                                             int row, unsigned sub) {
    int deg = g_cnt[row];
    if (deg > PAD_W) deg = PAD_W;
    const uint2* lst = g_list + (size_t)row * PAD_W;

    unsigned long long aA = 0ull, aB = 0ull;

    int j = 0;
    for (; j + 4 <= deg; j += 4) {                 // 4 edges / 32B load
        unsigned long long q0, q1, q2, q3;
        ldg_ef4(lst + j, q0, q1, q2, q3);
        uint2 x0 = src[(unsigned)q0 * 16u + sub];
        uint2 x1 = src[(unsigned)q1 * 16u + sub];
        uint2 x2 = src[(unsigned)q2 * 16u + sub];
        uint2 x3 = src[(unsigned)q3 * 16u + sub];
        unsigned long long v0 = dup_hi32(q0);
        unsigned long long v1 = dup_hi32(q1);
        unsigned long long v2 = dup_hi32(q2);
        unsigned long long v3 = dup_hi32(q3);
        fma2(aA, h2_to_fx2(x0.x), v0); fma2(aB, h2_to_fx2(x0.y), v0);
        fma2(aA, h2_to_fx2(x1.x), v1); fma2(aB, h2_to_fx2(x1.y), v1);
        fma2(aA, h2_to_fx2(x2.x), v2); fma2(aB, h2_to_fx2(x2.y), v2);
        fma2(aA, h2_to_fx2(x3.x), v3); fma2(aB, h2_to_fx2(x3.y), v3);
    }
    for (; j < deg; j++) {                         // tail (<= 3 edges)
        uint2 ent = lst[j];
        uint2 x = src[ent.x * 16u + sub];
        unsigned long long v;
        asm("mov.b64 %0, {%1, %1};" : "=l"(v) : "r"(ent.y));
        fma2(aA, h2_to_fx2(x.x), v);
        fma2(aB, h2_to_fx2(x.y), v);
    }

    int novf = g_ovf_cnt;                          // ~always 0
    if (novf > 0) {
        if (novf > OVF_CAP) novf = OVF_CAP;
        for (int k = 0; k < novf; k++) {
            int4 rec = g_ovf[k];
            if (rec.x == row) {
                unsigned long long v;
                asm("mov.b64 %0, {%1, %1};" : "=l"(v) : "r"((unsigned)rec.z));
                uint2 x = src[(unsigned)rec.y * 16u + sub];
                fma2(aA, h2_to_fx2(x.x), v);
                fma2(aB, h2_to_fx2(x.y), v);
            }
        }
    }

    float2 a = unpack_fx2(aA);
    float2 b = unpack_fx2(aB);
    return make_float4(a.x, a.y, b.x, b.y);
}

// ---- gather SpMM into a fp16 buffer ----------------------------------------
__global__ void lg_gather(const uint2* __restrict__ src,
                          uint2* __restrict__ dst, int n_rows) {
    int tid = blockIdx.x * blockDim.x + threadIdx.x;
    int row = tid >> 4;                  // 16 lanes per row
    unsigned sub = tid & 15;
    if (row >= n_rows) return;
    float4 acc = row_gather(src, row, sub);
    dst[(size_t)row * DIM4 + sub] = f4_to_h4(acc);
}

// ---- layer-3 gather fused with the final mean ------------------------------
__global__ void lg_gather_final(const uint2* __restrict__ src,    // e2 fp16
                                const float4* __restrict__ e0,
                                const uint2* __restrict__ h1,
                                const uint2* __restrict__ h2,
                                float4* __restrict__ out, int n_rows) {
    int tid = blockIdx.x * blockDim.x + threadIdx.x;
    int row = tid >> 4;
    unsigned sub = tid & 15;
    if (row >= n_rows) return;
    float4 acc = row_gather(src, row, sub);        // e3 in fp32 regs

    size_t idx = (size_t)row * DIM4 + sub;
    float4 v0 = e0[idx];
    uint2 x1 = h1[idx];
    uint2 x2 = h2[idx];
    float2 a1 = h2_to_f2(x1.x), b1 = h2_to_f2(x1.y);
    float2 a2 = h2_to_f2(x2.x), b2 = h2_to_f2(x2.y);

    float4 r;
    r.x = (v0.x + a1.x + a2.x + acc.x) * 0.25f;
    r.y = (v0.y + a1.y + a2.y + acc.y) * 0.25f;
    r.z = (v0.z + b1.x + b2.x + acc.z) * 0.25f;
    r.w = (v0.w + b1.y + b2.y + acc.w) * 0.25f;
    out[idx] = r;
}

extern "C" void kernel_launch(void* const* d_in, const int* in_sizes, int n_in,
                              void* d_out, int out_size) {
    const float* user = (const float*)d_in[0];
    const float* item = (const float*)d_in[1];
    const float* vals = (const float*)d_in[2];
    const int*   rows = (const int*)d_in[3];
    const int*   cols = (const int*)d_in[4];

    int n_user  = in_sizes[0] / DIM;
    int n_item  = in_sizes[1] / DIM;
    int nnz     = in_sizes[2];
    int n_total = n_user + n_item;
    int n4      = n_total * DIM4;

    float* out = (float*)d_out;

    float* e0; uint2* h0; uint2* h1; uint2* h2;
    cudaGetSymbolAddress((void**)&e0, g_e0);
    cudaGetSymbolAddress((void**)&h0, g_h0);
    cudaGetSymbolAddress((void**)&h1, g_h1);
    cudaGetSymbolAddress((void**)&h2, g_h2);

    int prep_blocks   = (n4 + TPB - 1) / TPB;
    int nq            = nnz >> 2;
    int build_blocks  = (nq + TPB - 1) / TPB;
    int gather_blocks = (n_total * 16 + TPB - 1) / TPB;   // 16 lanes/row

    lg_prep<<<prep_blocks, TPB>>>((const float4*)user, (const float4*)item,
                                  n_user * DIM4, n4, n_total);
    lg_build4<<<build_blocks, TPB>>>((const int4*)rows, (const int4*)cols,
                                     (const float4*)vals, rows, cols, vals,
                                     nq, nnz);

    lg_gather<<<gather_blocks, TPB>>>(h0, h1, n_total);            // e1
    lg_gather<<<gather_blocks, TPB>>>(h1, h2, n_total);            // e2
    lg_gather_final<<<gather_blocks, TPB>>>(h2, (const float4*)e0,
                                            h1, h2,
                                            (float4*)out, n_total); // e3+mean
}

// round 14
// speedup vs baseline: 1.2349x; 1.2349x over previous
#include <cuda_runtime.h>
#include <cuda_fp16.h>

// LightGCN propagation — gather formulation, fp16 sources, 8 lanes per row:
//   * fp16 embedding storage: 38.4MB table L2-resident, 128B line per edge
//   * 8 lanes per row (lane owns one uint4 = 8 halfs) -> 4 edges per warp
//     instruction; packed fma.rn.f32x2 accumulation (4 FMA2 / edge-lane)
//   * simple per-edge entry loads (R11-proven low-register skeleton)
// fp32 accumulation in registers; fp16 layer outputs; fp32 final mean reads
// the raw user/item inputs directly (no fp32 staging copy).
//
//   e0 = concat(user_emb, item_emb)   (N = 300000, D = 64)
//   e_{l+1}[r] = sum_{e: rows[e]==r} vals[e] * e_l[cols[e]]
//   out = (e0 + e1 + e2 + e3) / 4

#define DIM      64
#define DIM8     8               // uint4 (8-half) groups per row
#define PAD_W    32              // padded CSR width (deg ~ Poisson(13.3))
#define NMAX     300000
#define OVF_CAP  4096
#define TPB      256

// ---- static scratch (alloc-free rule) -------------------------------------
__device__ int   g_cnt[NMAX];                      // per-row degree/cursor
__device__ uint2 g_list[(size_t)NMAX * PAD_W];     // {col, val_bits}  76.8MB
__device__ int   g_ovf_cnt;
__device__ int4  g_ovf[OVF_CAP];                   // {row, col, val_bits, 0}
__device__ uint4 g_h0[(size_t)NMAX * DIM8];        // e0 fp16 (gather source)
__device__ uint4 g_h1[(size_t)NMAX * DIM8];        // e1 fp16
__device__ uint4 g_h2[(size_t)NMAX * DIM8];        // e2 fp16

// ---- packed helpers --------------------------------------------------------
__device__ __forceinline__ unsigned long long h2_to_fx2(unsigned h) {
    unsigned long long r;
    asm("{\n\t"
        ".reg .b16 lo, hi;\n\t"
        ".reg .f32 flo, fhi;\n\t"
        "mov.b32 {lo, hi}, %1;\n\t"
        "cvt.f32.f16 flo, lo;\n\t"
        "cvt.f32.f16 fhi, hi;\n\t"
        "mov.b64 %0, {flo, fhi};\n\t"
        "}" : "=l"(r) : "r"(h));
    return r;
}
__device__ __forceinline__ void fma2(unsigned long long& acc,
                                     unsigned long long x,
                                     unsigned long long v) {
    asm("fma.rn.f32x2 %0, %1, %2, %0;" : "+l"(acc) : "l"(x), "l"(v));
}
__device__ __forceinline__ unsigned long long dup32(unsigned v) {
    unsigned long long r;
    asm("mov.b64 %0, {%1, %1};" : "=l"(r) : "r"(v));
    return r;
}
__device__ __forceinline__ float2 unpack_fx2(unsigned long long a) {
    float2 r;
    asm("mov.b64 {%0, %1}, %2;" : "=f"(r.x), "=f"(r.y) : "l"(a));
    return r;
}
__device__ __forceinline__ unsigned f2_to_h2bits(float2 v) {
    __half2 h = __floats2half2_rn(v.x, v.y);
    return *reinterpret_cast<unsigned*>(&h);
}

struct Acc8 { unsigned long long a, b, c, d; };

// ---- prep: zero counters + e0 -> fp16 (8 floats -> one uint4 per thread) ---
__global__ void lg_prep(const float4* __restrict__ user,
                        const float4* __restrict__ item,
                        int n_user_f4, int n8, int n_rows) {
    int i = blockIdx.x * blockDim.x + threadIdx.x;
    if (i < n_rows) g_cnt[i] = 0;
    if (i == 0) g_ovf_cnt = 0;
    if (i >= n8) return;
    int f4i = i * 2;                 // first float4 index of this 8-float group
    float4 a, b;
    if (f4i < n_user_f4) { a = user[f4i]; b = user[f4i + 1]; }
    else { a = item[f4i - n_user_f4]; b = item[f4i - n_user_f4 + 1]; }
    uint4 h;
    h.x = f2_to_h2bits(make_float2(a.x, a.y));
    h.y = f2_to_h2bits(make_float2(a.z, a.w));
    h.z = f2_to_h2bits(make_float2(b.x, b.y));
    h.w = f2_to_h2bits(make_float2(b.z, b.w));
    g_h0[i] = h;
}

// ---- build padded CSR, 4 edges per thread ----------------------------------
__global__ void lg_build4(const int4* __restrict__ rows4,
                          const int4* __restrict__ cols4,
                          const float4* __restrict__ vals4,
                          const int* __restrict__ rows,
                          const int* __restrict__ cols,
                          const float* __restrict__ vals,
                          int nq, int nnz) {
    int i = blockIdx.x * blockDim.x + threadIdx.x;
    if (i < nq) {
        int4   r = rows4[i];
        int4   c = cols4[i];
        float4 v = vals4[i];
        int rr[4] = {r.x, r.y, r.z, r.w};
        int cc[4] = {c.x, c.y, c.z, c.w};
        float vv[4] = {v.x, v.y, v.z, v.w};
        #pragma unroll
        for (int k = 0; k < 4; k++) {
            int pos = atomicAdd(&g_cnt[rr[k]], 1);
            if (pos < PAD_W) {
                g_list[(size_t)rr[k] * PAD_W + pos] =
                    make_uint2((unsigned)cc[k], __float_as_uint(vv[k]));
            } else {
                int o = atomicAdd(&g_ovf_cnt, 1);
                if (o < OVF_CAP)
                    g_ovf[o] = make_int4(rr[k], cc[k], __float_as_int(vv[k]), 0);
            }
        }
    }
    if (i == 0) {                                   // scalar tail (<= 3 edges)
        for (int e = nq * 4; e < nnz; e++) {
            int pos = atomicAdd(&g_cnt[rows[e]], 1);
            if (pos < PAD_W) {
                g_list[(size_t)rows[e] * PAD_W + pos] =
                    make_uint2((unsigned)cols[e], __float_as_uint(vals[e]));
            } else {
                int o = atomicAdd(&g_ovf_cnt, 1);
                if (o < OVF_CAP)
                    g_ovf[o] = make_int4(rows[e], cols[e],
                                         __float_as_int(vals[e]), 0);
            }
        }
    }
}

// ---- per-row gather core: 8 lanes/row, fp16 src, packed f32x2 accum --------
__device__ __forceinline__ Acc8 row_gather(const uint4* __restrict__ src,
                                           int row, unsigned sub) {
    int deg = g_cnt[row];
    if (deg > PAD_W) deg = PAD_W;
    const uint2* lst = g_list + (size_t)row * PAD_W;

    Acc8 acc; acc.a = acc.b = acc.c = acc.d = 0ull;

    #pragma unroll 4
    for (int j = 0; j < deg; j++) {
        uint2 ent = lst[j];                        // uniform per 8-lane group
        unsigned long long v = dup32(ent.y);
        uint4 x = src[ent.x * 8u + sub];           // 16B: lane's 8 halfs
        fma2(acc.a, h2_to_fx2(x.x), v);
        fma2(acc.b, h2_to_fx2(x.y), v);
        fma2(acc.c, h2_to_fx2(x.z), v);
        fma2(acc.d, h2_to_fx2(x.w), v);
    }

    int novf = g_ovf_cnt;                          // ~always 0
    if (novf > 0) {
        if (novf > OVF_CAP) novf = OVF_CAP;
        for (int k = 0; k < novf; k++) {
            int4 rec = g_ovf[k];
            if (rec.x == row) {
                unsigned long long v = dup32((unsigned)rec.z);
                uint4 x = src[(unsigned)rec.y * 8u + sub];
                fma2(acc.a, h2_to_fx2(x.x), v);
                fma2(acc.b, h2_to_fx2(x.y), v);
                fma2(acc.c, h2_to_fx2(x.z), v);
                fma2(acc.d, h2_to_fx2(x.w), v);
            }
        }
    }
    return acc;
}

// ---- gather SpMM into a fp16 buffer ----------------------------------------
__global__ void lg_gather(const uint4* __restrict__ src,
                          uint4* __restrict__ dst, int n_rows) {
    int tid = blockIdx.x * blockDim.x + threadIdx.x;
    int row = tid >> 3;                  // 8 lanes per row
    unsigned sub = tid & 7;
    if (row >= n_rows) return;
    Acc8 acc = row_gather(src, row, sub);
    uint4 h;
    h.x = f2_to_h2bits(unpack_fx2(acc.a));
    h.y = f2_to_h2bits(unpack_fx2(acc.b));
    h.z = f2_to_h2bits(unpack_fx2(acc.c));
    h.w = f2_to_h2bits(unpack_fx2(acc.d));
    dst[(size_t)row * DIM8 + sub] = h;
}

// ---- layer-3 gather fused with the final mean ------------------------------
__global__ void lg_gather_final(const uint4* __restrict__ src,    // e2 fp16
                                const float4* __restrict__ user,
                                const float4* __restrict__ item, int n_user,
                                const uint4* __restrict__ h1,
                                const uint4* __restrict__ h2,
                                float4* __restrict__ out, int n_rows) {
    int tid = blockIdx.x * blockDim.x + threadIdx.x;
    int row = tid >> 3;
    unsigned sub = tid & 7;
    if (row >= n_rows) return;
    Acc8 acc = row_gather(src, row, sub);          // e3 in packed fp32

    size_t idx = (size_t)row * DIM8 + sub;
    const float4* b0 = (row < n_user)
        ? user + (size_t)row * 16 + sub * 2
        : item + (size_t)(row - n_user) * 16 + sub * 2;
    float4 v0a = b0[0];
    float4 v0b = b0[1];
    uint4 x1 = h1[idx];
    uint4 x2 = h2[idx];

    float2 e3a = unpack_fx2(acc.a), e3b = unpack_fx2(acc.b);
    float2 e3c = unpack_fx2(acc.c), e3d = unpack_fx2(acc.d);
    float2 a1 = __half22float2(*reinterpret_cast<__half2*>(&x1.x));
    float2 b1 = __half22float2(*reinterpret_cast<__half2*>(&x1.y));
    float2 c1 = __half22float2(*reinterpret_cast<__half2*>(&x1.z));
    float2 d1 = __half22float2(*reinterpret_cast<__half2*>(&x1.w));
    float2 a2 = __half22float2(*reinterpret_cast<__half2*>(&x2.x));
    float2 b2 = __half22float2(*reinterpret_cast<__half2*>(&x2.y));
    float2 c2 = __half22float2(*reinterpret_cast<__half2*>(&x2.z));
    float2 d2 = __half22float2(*reinterpret_cast<__half2*>(&x2.w));

    float4 r0, r1;
    r0.x = (v0a.x + a1.x + a2.x + e3a.x) * 0.25f;
    r0.y = (v0a.y + a1.y + a2.y + e3a.y) * 0.25f;
    r0.z = (v0a.z + b1.x + b2.x + e3b.x) * 0.25f;
    r0.w = (v0a.w + b1.y + b2.y + e3b.y) * 0.25f;
    r1.x = (v0b.x + c1.x + c2.x + e3c.x) * 0.25f;
    r1.y = (v0b.y + c1.y + c2.y + e3c.y) * 0.25f;
    r1.z = (v0b.z + d1.x + d2.x + e3d.x) * 0.25f;
    r1.w = (v0b.w + d1.y + d2.y + e3d.y) * 0.25f;

    float4* o = out + (size_t)row * 16 + sub * 2;
    o[0] = r0;
    o[1] = r1;
}

extern "C" void kernel_launch(void* const* d_in, const int* in_sizes, int n_in,
                              void* d_out, int out_size) {
    const float* user = (const float*)d_in[0];
    const float* item = (const float*)d_in[1];
    const float* vals = (const float*)d_in[2];
    const int*   rows = (const int*)d_in[3];
    const int*   cols = (const int*)d_in[4];

    int n_user  = in_sizes[0] / DIM;
    int n_item  = in_sizes[1] / DIM;
    int nnz     = in_sizes[2];
    int n_total = n_user + n_item;
    int n8      = n_total * DIM8;

    float* out = (float*)d_out;

    uint4* h0; uint4* h1; uint4* h2;
    cudaGetSymbolAddress((void**)&h0, g_h0);
    cudaGetSymbolAddress((void**)&h1, g_h1);
    cudaGetSymbolAddress((void**)&h2, g_h2);

    int prep_blocks   = (n8 + TPB - 1) / TPB;
    int nq            = nnz >> 2;
    int build_blocks  = (nq + TPB - 1) / TPB;
    int gather_blocks = (n_total * 8 + TPB - 1) / TPB;    // 8 lanes/row

    lg_prep<<<prep_blocks, TPB>>>((const float4*)user, (const float4*)item,
                                  n_user * 16, n8, n_total);
    lg_build4<<<build_blocks, TPB>>>((const int4*)rows, (const int4*)cols,
                                     (const float4*)vals, rows, cols, vals,
                                     nq, nnz);

    lg_gather<<<gather_blocks, TPB>>>(h0, h1, n_total);            // e1
    lg_gather<<<gather_blocks, TPB>>>(h1, h2, n_total);            // e2
    lg_gather_final<<<gather_blocks, TPB>>>(h2,
                                            (const float4*)user,
                                            (const float4*)item, n_user,
                                            h1, h2,
                                            (float4*)out, n_total); // e3+mean
}

// round 16
// speedup vs baseline: 1.2938x; 1.0477x over previous
#include <cuda_runtime.h>
#include <cuda_fp16.h>

// LightGCN propagation — gather formulation, fp16 sources:
//   R11 skeleton (16 lanes/row, 2 rows/warp, per-edge uint2 loads, 32 regs,
//   ~81% occupancy) + R14 math (packed cvt + fma.rn.f32x2: 2 FMA2 per
//   edge-lane instead of 4 FFMA). Latency-bound kernel -> protect occupancy
//   with __launch_bounds__, cut instructions between loads.
//
//   e0 = concat(user_emb, item_emb)   (N = 300000, D = 64)
//   e_{l+1}[r] = sum_{e: rows[e]==r} vals[e] * e_l[cols[e]]
//   out = (e0 + e1 + e2 + e3) / 4

#define DIM      64
#define DIM4     16              // 4-half (8B) groups per row
#define PAD_W    32              // padded CSR width (deg ~ Poisson(13.3))
#define NMAX     300000
#define OVF_CAP  4096
#define TPB      256

// ---- static scratch (alloc-free rule) -------------------------------------
__device__ int   g_cnt[NMAX];                      // per-row degree/cursor
__device__ uint2 g_list[(size_t)NMAX * PAD_W];     // {col, val_bits}  76.8MB
__device__ int   g_ovf_cnt;
__device__ int4  g_ovf[OVF_CAP];                   // {row, col, val_bits, 0}
__device__ uint2 g_h0[(size_t)NMAX * DIM4];        // e0 fp16 (gather source)
__device__ uint2 g_h1[(size_t)NMAX * DIM4];        // e1 fp16
__device__ uint2 g_h2[(size_t)NMAX * DIM4];        // e2 fp16

// ---- packed helpers --------------------------------------------------------
__device__ __forceinline__ unsigned long long h2_to_fx2(unsigned h) {
    unsigned long long r;
    asm("{\n\t"
        ".reg .b16 lo, hi;\n\t"
        ".reg .f32 flo, fhi;\n\t"
        "mov.b32 {lo, hi}, %1;\n\t"
        "cvt.f32.f16 flo, lo;\n\t"
        "cvt.f32.f16 fhi, hi;\n\t"
        "mov.b64 %0, {flo, fhi};\n\t"
        "}" : "=l"(r) : "r"(h));
    return r;
}
__device__ __forceinline__ void fma2(unsigned long long& acc,
                                     unsigned long long x,
                                     unsigned long long v) {
    asm("fma.rn.f32x2 %0, %1, %2, %0;" : "+l"(acc) : "l"(x), "l"(v));
}
__device__ __forceinline__ unsigned long long dup32(unsigned v) {
    unsigned long long r;
    asm("mov.b64 %0, {%1, %1};" : "=l"(r) : "r"(v));
    return r;
}
__device__ __forceinline__ float2 unpack_fx2(unsigned long long a) {
    float2 r;
    asm("mov.b64 {%0, %1}, %2;" : "=f"(r.x), "=f"(r.y) : "l"(a));
    return r;
}
__device__ __forceinline__ unsigned f2_to_h2bits(float2 v) {
    __half2 h = __floats2half2_rn(v.x, v.y);
    return *reinterpret_cast<unsigned*>(&h);
}

// ---- prep: zero counters + convert e0 -> fp16 ------------------------------
__global__ void lg_prep(const float4* __restrict__ user,
                        const float4* __restrict__ item,
                        int n_user4, int n4, int n_rows) {
    int i = blockIdx.x * blockDim.x + threadIdx.x;
    if (i < n_rows) g_cnt[i] = 0;
    if (i == 0) g_ovf_cnt = 0;
    if (i >= n4) return;
    float4 v = (i < n_user4) ? user[i] : item[i - n_user4];
    uint2 h;
    h.x = f2_to_h2bits(make_float2(v.x, v.y));
    h.y = f2_to_h2bits(make_float2(v.z, v.w));
    g_h0[i] = h;
}

// ---- build padded CSR, 4 edges per thread ----------------------------------
__global__ void lg_build4(const int4* __restrict__ rows4,
                          const int4* __restrict__ cols4,
                          const float4* __restrict__ vals4,
                          const int* __restrict__ rows,
                          const int* __restrict__ cols,
                          const float* __restrict__ vals,
                          int nq, int nnz) {
    int i = blockIdx.x * blockDim.x + threadIdx.x;
    if (i < nq) {
        int4   r = rows4[i];
        int4   c = cols4[i];
        float4 v = vals4[i];
        int rr[4] = {r.x, r.y, r.z, r.w};
        int cc[4] = {c.x, c.y, c.z, c.w};
        float vv[4] = {v.x, v.y, v.z, v.w};
        #pragma unroll
        for (int k = 0; k < 4; k++) {
            int pos = atomicAdd(&g_cnt[rr[k]], 1);
            if (pos < PAD_W) {
                g_list[(size_t)rr[k] * PAD_W + pos] =
                    make_uint2((unsigned)cc[k], __float_as_uint(vv[k]));
            } else {
                int o = atomicAdd(&g_ovf_cnt, 1);
                if (o < OVF_CAP)
                    g_ovf[o] = make_int4(rr[k], cc[k], __float_as_int(vv[k]), 0);
            }
        }
    }
    if (i == 0) {                                   // scalar tail (<= 3 edges)
        for (int e = nq * 4; e < nnz; e++) {
            int pos = atomicAdd(&g_cnt[rows[e]], 1);
            if (pos < PAD_W) {
                g_list[(size_t)rows[e] * PAD_W + pos] =
                    make_uint2((unsigned)cols[e], __float_as_uint(vals[e]));
            } else {
                int o = atomicAdd(&g_ovf_cnt, 1);
                if (o < OVF_CAP)
                    g_ovf[o] = make_int4(rows[e], cols[e],
                                         __float_as_int(vals[e]), 0);
            }
        }
    }
}

// ---- per-row gather core: 16 lanes/row, fp16 src, packed f32x2 accum -------
__device__ __forceinline__ void row_gather(const uint2* __restrict__ src,
                                           int row, unsigned sub,
                                           unsigned long long& aA,
                                           unsigned long long& aB) {
    int deg = g_cnt[row];
    if (deg > PAD_W) deg = PAD_W;
    const uint2* lst = g_list + (size_t)row * PAD_W;

    #pragma unroll 4
    for (int j = 0; j < deg; j++) {
        uint2 ent = lst[j];                        // uniform per half-warp
        unsigned long long v = dup32(ent.y);
        uint2 x = src[ent.x * 16u + sub];          // 8B: lane's 4 halfs
        fma2(aA, h2_to_fx2(x.x), v);
        fma2(aB, h2_to_fx2(x.y), v);
    }

    int novf = g_ovf_cnt;                          // ~always 0
    if (novf > 0) {
        if (novf > OVF_CAP) novf = OVF_CAP;
        for (int k = 0; k < novf; k++) {
            int4 rec = g_ovf[k];
            if (rec.x == row) {
                unsigned long long v = dup32((unsigned)rec.z);
                uint2 x = src[(unsigned)rec.y * 16u + sub];
                fma2(aA, h2_to_fx2(x.x), v);
                fma2(aB, h2_to_fx2(x.y), v);
            }
        }
    }
}

// ---- gather SpMM into a fp16 buffer ----------------------------------------
__global__ void __launch_bounds__(TPB, 8)
lg_gather(const uint2* __restrict__ src, uint2* __restrict__ dst, int n_rows) {
    int tid = blockIdx.x * blockDim.x + threadIdx.x;
    int row = tid >> 4;                  // 16 lanes per row
    unsigned sub = tid & 15;
    if (row >= n_rows) return;
    unsigned long long aA = 0ull, aB = 0ull;
    row_gather(src, row, sub, aA, aB);
    uint2 h;
    h.x = f2_to_h2bits(unpack_fx2(aA));
    h.y = f2_to_h2bits(unpack_fx2(aB));
    dst[(size_t)row * DIM4 + sub] = h;
}

// ---- layer-3 gather fused with the final mean ------------------------------
__global__ void __launch_bounds__(TPB, 8)
lg_gather_final(const uint2* __restrict__ src,    // e2 fp16
                const float4* __restrict__ user,
                const float4* __restrict__ item, int n_user,
                const uint2* __restrict__ h1,
                const uint2* __restrict__ h2,
                float4* __restrict__ out, int n_rows) {
    int tid = blockIdx.x * blockDim.x + threadIdx.x;
    int row = tid >> 4;
    unsigned sub = tid & 15;
    if (row >= n_rows) return;
    unsigned long long aA = 0ull, aB = 0ull;
    row_gather(src, row, sub, aA, aB);             // e3 in packed fp32

    size_t idx = (size_t)row * DIM4 + sub;
    float4 v0 = (row < n_user) ? user[(size_t)row * DIM4 + sub]
                               : item[(size_t)(row - n_user) * DIM4 + sub];
    uint2 x1 = h1[idx];
    uint2 x2 = h2[idx];
    float2 e3a = unpack_fx2(aA), e3b = unpack_fx2(aB);
    float2 a1 = __half22float2(*reinterpret_cast<__half2*>(&x1.x));
    float2 b1 = __half22float2(*reinterpret_cast<__half2*>(&x1.y));
    float2 a2 = __half22float2(*reinterpret_cast<__half2*>(&x2.x));
    float2 b2 = __half22float2(*reinterpret_cast<__half2*>(&x2.y));

    float4 r;
    r.x = (v0.x + a1.x + a2.x + e3a.x) * 0.25f;
    r.y = (v0.y + a1.y + a2.y + e3a.y) * 0.25f;
    r.z = (v0.z + b1.x + b2.x + e3b.x) * 0.25f;
    r.w = (v0.w + b1.y + b2.y + e3b.y) * 0.25f;
    out[idx] = r;
}

extern "C" void kernel_launch(void* const* d_in, const int* in_sizes, int n_in,
                              void* d_out, int out_size) {
    const float* user = (const float*)d_in[0];
    const float* item = (const float*)d_in[1];
    const float* vals = (const float*)d_in[2];
    const int*   rows = (const int*)d_in[3];
    const int*   cols = (const int*)d_in[4];

    int n_user  = in_sizes[0] / DIM;
    int n_item  = in_sizes[1] / DIM;
    int nnz     = in_sizes[2];
    int n_total = n_user + n_item;
    int n4      = n_total * DIM4;

    float* out = (float*)d_out;

    uint2* h0; uint2* h1; uint2* h2;
    cudaGetSymbolAddress((void**)&h0, g_h0);
    cudaGetSymbolAddress((void**)&h1, g_h1);
    cudaGetSymbolAddress((void**)&h2, g_h2);

    int prep_blocks   = (n4 + TPB - 1) / TPB;
    int nq            = nnz >> 2;
    int build_blocks  = (nq + TPB - 1) / TPB;
    int gather_blocks = (n_total * 16 + TPB - 1) / TPB;   // 16 lanes/row

    lg_prep<<<prep_blocks, TPB>>>((const float4*)user, (const float4*)item,
                                  n_user * DIM4, n4, n_total);
    lg_build4<<<build_blocks, TPB>>>((const int4*)rows, (const int4*)cols,
                                     (const float4*)vals, rows, cols, vals,
                                     nq, nnz);

    lg_gather<<<gather_blocks, TPB>>>(h0, h1, n_total);            // e1
    lg_gather<<<gather_blocks, TPB>>>(h1, h2, n_total);            // e2
    lg_gather_final<<<gather_blocks, TPB>>>(h2,
                                            (const float4*)user,
                                            (const float4*)item, n_user,
                                            h1, h2,
                                            (float4*)out, n_total); // e3+mean
}